// round 14
// baseline (speedup 1.0000x reference)
#include <cuda_runtime.h>
#include <cuda_bf16.h>
#include <cuda_fp16.h>
#include <math.h>
#include <stdint.h>

#define N_NODES 50000
#define N_EDGES 600000
#define LATENT  128
#define IN_FEAT 7
#define STEPS   3

// ---------------- scratch (no allocations allowed) ----------------
__device__ float   g_h   [N_NODES * LATENT];
__device__ __half  g_x1h [N_NODES * LATENT];   // fp16 layer-1 activations
__device__ __half  g_x2h [N_NODES * LATENT];   // fp16 MLP output for gather
__device__ float   g_invs[N_NODES];
__device__ float   g_invr[N_NODES];
__device__ int     g_cnt_s[N_NODES];
__device__ int     g_cnt_r[N_NODES];
__device__ int     g_rowstart[N_NODES + 1];
__device__ int     g_cursor[N_NODES];
__device__ int     g_elist[N_EDGES];
// transposed bf16 weight images: per weight [hi 16384 bf16 | lo 16384 bf16]
__device__ uint32_t g_wimg[STEPS * 2 * 16384];

// ---------------- helpers ----------------
__device__ __forceinline__ uint32_t smem_u32(const void* p) {
    uint32_t a;
    asm("{ .reg .u64 t; cvta.to.shared.u64 t, %1; cvt.u32.u64 %0, t; }"
        : "=r"(a) : "l"(p));
    return a;
}
__device__ __forceinline__ void ldsm4(uint32_t* r, uint32_t addr) {
    asm volatile("ldmatrix.sync.aligned.m8n8.x4.shared.b16 {%0,%1,%2,%3}, [%4];"
                 : "=r"(r[0]), "=r"(r[1]), "=r"(r[2]), "=r"(r[3]) : "r"(addr));
}
__device__ __forceinline__ void mma16816(float* c, const uint32_t* a,
                                         uint32_t b0, uint32_t b1) {
    asm volatile("mma.sync.aligned.m16n8k16.row.col.f32.bf16.bf16.f32 "
                 "{%0,%1,%2,%3}, {%4,%5,%6,%7}, {%8,%9}, {%0,%1,%2,%3};"
                 : "+f"(c[0]), "+f"(c[1]), "+f"(c[2]), "+f"(c[3])
                 : "r"(a[0]), "r"(a[1]), "r"(a[2]), "r"(a[3]), "r"(b0), "r"(b1));
}

// ---------------- degree counting ----------------
__global__ void degree_kernel(const int* __restrict__ senders,
                              const int* __restrict__ receivers) {
    int e = blockIdx.x * blockDim.x + threadIdx.x;
    if (e >= N_EDGES) return;
    atomicAdd(&g_cnt_s[senders[e]],   1);
    atomicAdd(&g_cnt_r[receivers[e]], 1);
}

// ---------------- CSR build: scan + fill (+ invsqrt fused) ----------------
__global__ void scan_kernel() {   // single block, 1024 threads
    __shared__ int part[1024];
    const int t = threadIdx.x;
    const int CH = (N_NODES + 1023) / 1024;
    const int base = t * CH;
    int s = 0;
    for (int i = 0; i < CH; i++) {
        int idx = base + i;
        if (idx < N_NODES) s += g_cnt_r[idx];
    }
    part[t] = s;
    __syncthreads();
    for (int off = 1; off < 1024; off <<= 1) {
        int v = (t >= off) ? part[t - off] : 0;
        __syncthreads();
        part[t] += v;
        __syncthreads();
    }
    int run = (t == 0) ? 0 : part[t - 1];
    for (int i = 0; i < CH; i++) {
        int idx = base + i;
        if (idx < N_NODES) {
            g_rowstart[idx] = run;
            run += g_cnt_r[idx];
            g_cursor[idx] = 0;
            g_invs[idx] = rsqrtf(fmaxf((float)g_cnt_s[idx], 1.0f));
            g_invr[idx] = rsqrtf(fmaxf((float)g_cnt_r[idx], 1.0f));
        }
    }
    if (t == 1023) g_rowstart[N_NODES] = run;
}

__global__ void fill_kernel(const int* __restrict__ senders,
                            const int* __restrict__ receivers) {
    int e = blockIdx.x * blockDim.x + threadIdx.x;
    if (e >= N_EDGES) return;
    int r = receivers[e];
    int pos = atomicAdd(&g_cursor[r], 1);
    g_elist[g_rowstart[r] + pos] = senders[e];
}

// ---------------- embed (vectorized): h = nodes @ W_embed + b ----------------
__global__ void embed_kernel(const float* __restrict__ nodes,
                             const float* __restrict__ We,
                             const float* __restrict__ be) {
    int idx = blockIdx.x * blockDim.x + threadIdx.x;   // N_NODES * 32
    if (idx >= N_NODES * 32) return;
    int n  = idx >> 5;
    int c4 = (idx & 31) * 4;
    float4 acc = *(const float4*)&be[c4];
#pragma unroll
    for (int k = 0; k < IN_FEAT; k++) {
        float nk = nodes[n * IN_FEAT + k];
        float4 w = *(const float4*)&We[k * LATENT + c4];
        acc.x = fmaf(nk, w.x, acc.x);
        acc.y = fmaf(nk, w.y, acc.y);
        acc.z = fmaf(nk, w.z, acc.z);
        acc.w = fmaf(nk, w.w, acc.w);
    }
    *(float4*)&g_h[(size_t)n * LATENT + c4] = acc;
}

// ---------------- W prep: transpose + bf16 hi/lo split ----------------
__global__ void wprep_kernel(const float* __restrict__ mlp_W) {
    int idx = blockIdx.x * blockDim.x + threadIdx.x;  // 6 * 16384
    if (idx >= STEPS * 2 * LATENT * LATENT) return;
    int w = idx >> 14;
    int e = idx & 16383;
    int k = e >> 7;
    int n = e & 127;
    float val = mlp_W[(size_t)w * 16384 + k * 128 + n];
    __nv_bfloat16 h = __float2bfloat16(val);
    __nv_bfloat16 l = __float2bfloat16(val - __bfloat162float(h));
    uint16_t* hi = (uint16_t*)&g_wimg[(size_t)w * 16384];
    uint16_t* lo = hi + 16384;
    hi[n * 128 + k] = *(uint16_t*)&h;
    lo[n * 128 + k] = *(uint16_t*)&l;
}

// ---------------- HMMA bf16x3 GEMM ----------------
#define STR 136
#define SM_A_HI 0
#define SM_A_LO (128 * STR * 2)
#define SM_W_HI (2 * 128 * STR * 2)
#define SM_W_LO (3 * 128 * STR * 2)
#define SM_TOTAL (4 * 128 * STR * 2)     // 139264 bytes

// in_half: A is __half[N][128] (else float).  out_half: C is __half[N][128] (else float).
__global__ void __launch_bounds__(256)
gemm_mma_kernel(const void* __restrict__ Ain,
                const uint32_t* __restrict__ Wimg,
                const float* __restrict__ bias,
                const float* __restrict__ rowscale,
                void* __restrict__ Cout, int N, int in_half, int out_half) {
    extern __shared__ __align__(16) char smem[];
    const uint32_t sb = smem_u32(smem);
    const int t = threadIdx.x, lane = t & 31, wid = t >> 5;
    const int warp_m = wid >> 1;
    const int warp_n = wid & 1;
    const int row0 = blockIdx.x * 128;

    // stage W images (repad 64 -> 68 u32/row)
    {
        uint32_t* dh = (uint32_t*)(smem + SM_W_HI);
        uint32_t* dl = (uint32_t*)(smem + SM_W_LO);
        const uint32_t* shi = Wimg;
        const uint32_t* slo = Wimg + 8192;
#pragma unroll
        for (int i = 0; i < 32; i++) {
            int idx = t + i * 256;
            int n  = idx >> 6;
            int kp = idx & 63;
            dh[n * (STR / 2) + kp] = shi[idx];
            dl[n * (STR / 2) + kp] = slo[idx];
        }
    }

    // stage A: fp32/fp16 -> bf16 hi/lo
    {
        int row  = t >> 1;
        int k0   = (t & 1) * 64;
        int grow = row0 + row;
        uint32_t* dh = (uint32_t*)(smem + SM_A_HI);
        uint32_t* dl = (uint32_t*)(smem + SM_A_LO);
#pragma unroll
        for (int q = 0; q < 16; q++) {
            float f[4];
            if (in_half) {
                const __half* Ah = (const __half*)Ain;
                uint2 u = (grow < N)
                    ? *(const uint2*)&Ah[(size_t)grow * 128 + k0 + q * 4]
                    : make_uint2(0u, 0u);
                float2 f01 = __half22float2(*(__half2*)&u.x);
                float2 f23 = __half22float2(*(__half2*)&u.y);
                f[0] = f01.x; f[1] = f01.y; f[2] = f23.x; f[3] = f23.y;
            } else {
                const float* Af = (const float*)Ain;
                float4 v = (grow < N)
                    ? *(const float4*)&Af[(size_t)grow * 128 + k0 + q * 4]
                    : make_float4(0.f, 0.f, 0.f, 0.f);
                f[0] = v.x; f[1] = v.y; f[2] = v.z; f[3] = v.w;
            }
#pragma unroll
            for (int p = 0; p < 2; p++) {
                int k = k0 + q * 4 + p * 2;
                __nv_bfloat16 h0 = __float2bfloat16(f[p * 2 + 0]);
                __nv_bfloat16 h1 = __float2bfloat16(f[p * 2 + 1]);
                __nv_bfloat16 l0 = __float2bfloat16(f[p * 2 + 0] - __bfloat162float(h0));
                __nv_bfloat16 l1 = __float2bfloat16(f[p * 2 + 1] - __bfloat162float(h1));
                uint32_t hp = (uint32_t)*(uint16_t*)&h0 | ((uint32_t)*(uint16_t*)&h1 << 16);
                uint32_t lp = (uint32_t)*(uint16_t*)&l0 | ((uint32_t)*(uint16_t*)&l1 << 16);
                dh[row * (STR / 2) + k / 2] = hp;
                dl[row * (STR / 2) + k / 2] = lp;
            }
        }
    }
    __syncthreads();

    float acc[2][8][4];
#pragma unroll
    for (int i = 0; i < 2; i++)
#pragma unroll
        for (int j = 0; j < 8; j++)
#pragma unroll
            for (int q = 0; q < 4; q++) acc[i][j][q] = 0.0f;

    const int a_row_l = (lane & 15);
    const int a_koff  = (lane >> 4) * 8;
    const int b_row_l = ((lane >> 4) & 1) * 8 + (lane & 7);
    const int b_koff  = ((lane >> 3) & 1) * 8;

#pragma unroll
    for (int term = 0; term < 3; term++) {
        const uint32_t aBase = sb + ((term == 2) ? SM_A_LO : SM_A_HI);
        const uint32_t wBase = sb + ((term == 1) ? SM_W_LO : SM_W_HI);
#pragma unroll
        for (int ks = 0; ks < 8; ks++) {
            const int k = ks * 16;
            uint32_t a[2][4];
#pragma unroll
            for (int i = 0; i < 2; i++) {
                int r = warp_m * 32 + i * 16 + a_row_l;
                ldsm4(a[i], aBase + (uint32_t)(r * STR + k + a_koff) * 2);
            }
            uint32_t b[4][4];
#pragma unroll
            for (int jj = 0; jj < 4; jj++) {
                int nr = warp_n * 64 + jj * 16 + b_row_l;
                ldsm4(b[jj], wBase + (uint32_t)(nr * STR + k + b_koff) * 2);
            }
#pragma unroll
            for (int i = 0; i < 2; i++)
#pragma unroll
                for (int j = 0; j < 8; j++)
                    mma16816(acc[i][j], a[i], b[j >> 1][(j & 1) * 2],
                             b[j >> 1][(j & 1) * 2 + 1]);
        }
    }

#pragma unroll
    for (int i = 0; i < 2; i++) {
        int r0 = row0 + warp_m * 32 + i * 16 + (lane >> 2);
        int r1 = r0 + 8;
        float rs0 = 1.0f, rs1 = 1.0f;
        if (rowscale) {
            if (r0 < N) rs0 = rowscale[r0];
            if (r1 < N) rs1 = rowscale[r1];
        }
#pragma unroll
        for (int j = 0; j < 8; j++) {
            int col = warp_n * 64 + j * 8 + (lane & 3) * 2;
            float2 bv = *(const float2*)&bias[col];
            float ox0 = fmaxf(acc[i][j][0] + bv.x, 0.f) * rs0;
            float oy0 = fmaxf(acc[i][j][1] + bv.y, 0.f) * rs0;
            float ox1 = fmaxf(acc[i][j][2] + bv.x, 0.f) * rs1;
            float oy1 = fmaxf(acc[i][j][3] + bv.y, 0.f) * rs1;
            if (out_half) {
                __half* Ch = (__half*)Cout;
                if (r0 < N) {
                    __half2 hh = __floats2half2_rn(ox0, oy0);
                    *(__half2*)&Ch[(size_t)r0 * 128 + col] = hh;
                }
                if (r1 < N) {
                    __half2 hh = __floats2half2_rn(ox1, oy1);
                    *(__half2*)&Ch[(size_t)r1 * 128 + col] = hh;
                }
            } else {
                float* Cf = (float*)Cout;
                if (r0 < N) { float2 o = {ox0, oy0}; *(float2*)&Cf[(size_t)r0 * 128 + col] = o; }
                if (r1 < N) { float2 o = {ox1, oy1}; *(float2*)&Cf[(size_t)r1 * 128 + col] = o; }
            }
        }
    }
}

// ---------------- fused CSR gather (fp16) + skip + LayerNorm (warp per node) ----------------
__global__ void agg_ln_kernel(const float* __restrict__ scale,
                              const float* __restrict__ bias) {
    int gid  = blockIdx.x * blockDim.x + threadIdx.x;
    int n    = gid >> 5;
    int lane = gid & 31;
    if (n >= N_NODES) return;

    const int beg = g_rowstart[n];
    const int end = g_rowstart[n + 1];

    const uint2* x2v = (const uint2*)g_x2h;   // 4 halves per uint2, 32 per row

    float a0 = 0.f, a1 = 0.f, a2 = 0.f, a3 = 0.f;
    int i = beg;
    for (; i + 1 < end; i += 2) {
        int s0 = g_elist[i];
        int s1 = g_elist[i + 1];
        uint2 u0 = x2v[(size_t)s0 * 32 + lane];
        uint2 u1 = x2v[(size_t)s1 * 32 + lane];
        float2 p00 = __half22float2(*(__half2*)&u0.x);
        float2 p01 = __half22float2(*(__half2*)&u0.y);
        float2 p10 = __half22float2(*(__half2*)&u1.x);
        float2 p11 = __half22float2(*(__half2*)&u1.y);
        a0 += p00.x + p10.x;
        a1 += p00.y + p10.y;
        a2 += p01.x + p11.x;
        a3 += p01.y + p11.y;
    }
    if (i < end) {
        int s0 = g_elist[i];
        uint2 u0 = x2v[(size_t)s0 * 32 + lane];
        float2 p00 = __half22float2(*(__half2*)&u0.x);
        float2 p01 = __half22float2(*(__half2*)&u0.y);
        a0 += p00.x; a1 += p00.y; a2 += p01.x; a3 += p01.y;
    }

    float ir = g_invr[n];
    float4 hv = *(const float4*)&g_h[(size_t)n * LATENT + lane * 4];
    float v0 = hv.x + a0 * ir;
    float v1 = hv.y + a1 * ir;
    float v2 = hv.z + a2 * ir;
    float v3 = hv.w + a3 * ir;

    float sum = v0 + v1 + v2 + v3;
    float sq  = v0 * v0 + v1 * v1 + v2 * v2 + v3 * v3;
#pragma unroll
    for (int o = 16; o > 0; o >>= 1) {
        sum += __shfl_xor_sync(0xFFFFFFFF, sum, o);
        sq  += __shfl_xor_sync(0xFFFFFFFF, sq,  o);
    }
    float mean = sum * (1.0f / LATENT);
    float var  = sq * (1.0f / LATENT) - mean * mean;
    float rstd = rsqrtf(var + 1e-6f);
    float4 sc = *(const float4*)&scale[lane * 4];
    float4 bi = *(const float4*)&bias[lane * 4];
    float4 o4;
    o4.x = (v0 - mean) * rstd * sc.x + bi.x;
    o4.y = (v1 - mean) * rstd * sc.y + bi.y;
    o4.z = (v2 - mean) * rstd * sc.z + bi.z;
    o4.w = (v3 - mean) * rstd * sc.w + bi.w;
    *(float4*)&g_h[(size_t)n * LATENT + lane * 4] = o4;
}

// ---------------- decode: out = h @ W_dec + b_dec (warp per node) ----------------
__global__ void decode_kernel(const float* __restrict__ Wd,
                              const float* __restrict__ bd,
                              float* __restrict__ out) {
    int gid  = blockIdx.x * blockDim.x + threadIdx.x;
    int n    = gid >> 5;
    int lane = gid & 31;
    if (n >= N_NODES) return;
    float4 hv = *(const float4*)&g_h[(size_t)n * LATENT + lane * 4];
    float h[4] = {hv.x, hv.y, hv.z, hv.w};
    float acc[IN_FEAT];
#pragma unroll
    for (int o = 0; o < IN_FEAT; o++) acc[o] = 0.0f;
#pragma unroll
    for (int q = 0; q < 4; q++) {
        int k = lane * 4 + q;
#pragma unroll
        for (int o = 0; o < IN_FEAT; o++)
            acc[o] = fmaf(h[q], Wd[k * IN_FEAT + o], acc[o]);
    }
#pragma unroll
    for (int o = 0; o < IN_FEAT; o++) {
#pragma unroll
        for (int off = 16; off > 0; off >>= 1)
            acc[o] += __shfl_xor_sync(0xFFFFFFFF, acc[o], off);
    }
    if (lane < IN_FEAT)
        out[n * IN_FEAT + lane] = acc[lane] + bd[lane];
}

// ---------------- host launch ----------------
extern "C" void kernel_launch(void* const* d_in, const int* in_sizes, int n_in,
                              void* d_out, int out_size) {
    const float* nodes     = (const float*)d_in[0];
    const int*   senders   = (const int*)  d_in[1];
    const int*   receivers = (const int*)  d_in[2];
    const float* W_embed   = (const float*)d_in[3];
    const float* b_embed   = (const float*)d_in[4];
    const float* mlp_W     = (const float*)d_in[5];
    const float* mlp_b     = (const float*)d_in[6];
    const float* ln_scale  = (const float*)d_in[7];
    const float* ln_bias   = (const float*)d_in[8];
    const float* W_dec     = (const float*)d_in[9];
    const float* b_dec     = (const float*)d_in[10];
    float* out = (float*)d_out;

    void *p_h, *p_x1h, *p_x2h, *p_invs, *p_cs, *p_cr, *p_wimg;
    cudaGetSymbolAddress(&p_h,    g_h);
    cudaGetSymbolAddress(&p_x1h,  g_x1h);
    cudaGetSymbolAddress(&p_x2h,  g_x2h);
    cudaGetSymbolAddress(&p_invs, g_invs);
    cudaGetSymbolAddress(&p_cs,   g_cnt_s);
    cudaGetSymbolAddress(&p_cr,   g_cnt_r);
    cudaGetSymbolAddress(&p_wimg, g_wimg);

    cudaFuncSetAttribute(gemm_mma_kernel,
                         cudaFuncAttributeMaxDynamicSharedMemorySize, SM_TOTAL);

    // CSR + normalization prologue
    cudaMemsetAsync(p_cs, 0, N_NODES * sizeof(int), 0);
    cudaMemsetAsync(p_cr, 0, N_NODES * sizeof(int), 0);
    degree_kernel<<<(N_EDGES + 255) / 256, 256>>>(senders, receivers);
    scan_kernel<<<1, 1024>>>();
    fill_kernel<<<(N_EDGES + 255) / 256, 256>>>(senders, receivers);

    // weight images + embed
    wprep_kernel<<<(STEPS * 2 * LATENT * LATENT + 255) / 256, 256>>>(mlp_W);
    embed_kernel<<<(N_NODES * 32 + 255) / 256, 256>>>(nodes, W_embed, b_embed);

    const int gemm_grid = (N_NODES + 127) / 128;
    const int ln_grid = (N_NODES * 32 + 255) / 256;

    for (int step = 0; step < STEPS; step++) {
        const float* b0 = mlp_b + ((size_t)step * 2 + 0) * LATENT;
        const float* b1 = mlp_b + ((size_t)step * 2 + 1) * LATENT;
        const uint32_t* img0 = (const uint32_t*)p_wimg + (size_t)(step * 2 + 0) * 16384;
        const uint32_t* img1 = (const uint32_t*)p_wimg + (size_t)(step * 2 + 1) * 16384;

        gemm_mma_kernel<<<gemm_grid, 256, SM_TOTAL>>>(p_h, img0, b0,
                                                      nullptr, p_x1h, N_NODES, 0, 1);
        gemm_mma_kernel<<<gemm_grid, 256, SM_TOTAL>>>(p_x1h, img1, b1,
                                                      (const float*)p_invs,
                                                      p_x2h, N_NODES, 1, 1);
        agg_ln_kernel<<<ln_grid, 256>>>(ln_scale + step * LATENT, ln_bias + step * LATENT);
    }

    decode_kernel<<<ln_grid, 256>>>(W_dec, b_dec, out);
}

// round 15
// speedup vs baseline: 1.2710x; 1.2710x over previous
#include <cuda_runtime.h>
#include <cuda_bf16.h>
#include <cuda_fp16.h>
#include <math.h>
#include <stdint.h>

#define N_NODES 50000
#define N_EDGES 600000
#define LATENT  128
#define IN_FEAT 7
#define STEPS   3

// ---------------- scratch (no allocations allowed) ----------------
__device__ float   g_h   [N_NODES * LATENT];
__device__ float   g_x1  [N_NODES * LATENT];
__device__ __half  g_x2h [N_NODES * LATENT];   // fp16 MLP output for gather
__device__ float   g_invs[N_NODES];
__device__ float   g_invr[N_NODES];
__device__ int     g_cnt_s[N_NODES];
__device__ int     g_cnt_r[N_NODES];
__device__ int     g_rowstart[N_NODES + 1];
__device__ int     g_epos[N_EDGES];
__device__ int     g_elist[N_EDGES];
// transposed bf16 weight images: per weight [hi 16384 bf16 | lo 16384 bf16]
__device__ uint32_t g_wimg[STEPS * 2 * 16384];

// ---------------- helpers ----------------
__device__ __forceinline__ uint32_t smem_u32(const void* p) {
    uint32_t a;
    asm("{ .reg .u64 t; cvta.to.shared.u64 t, %1; cvt.u32.u64 %0, t; }"
        : "=r"(a) : "l"(p));
    return a;
}
__device__ __forceinline__ void ldsm4(uint32_t* r, uint32_t addr) {
    asm volatile("ldmatrix.sync.aligned.m8n8.x4.shared.b16 {%0,%1,%2,%3}, [%4];"
                 : "=r"(r[0]), "=r"(r[1]), "=r"(r[2]), "=r"(r[3]) : "r"(addr));
}
__device__ __forceinline__ void mma16816(float* c, const uint32_t* a,
                                         uint32_t b0, uint32_t b1) {
    asm volatile("mma.sync.aligned.m16n8k16.row.col.f32.bf16.bf16.f32 "
                 "{%0,%1,%2,%3}, {%4,%5,%6,%7}, {%8,%9}, {%0,%1,%2,%3};"
                 : "+f"(c[0]), "+f"(c[1]), "+f"(c[2]), "+f"(c[3])
                 : "r"(a[0]), "r"(a[1]), "r"(a[2]), "r"(a[3]), "r"(b0), "r"(b1));
}

// ---------------- degree counting (also records per-edge slot) ----------------
__global__ void degree_kernel(const int* __restrict__ senders,
                              const int* __restrict__ receivers) {
    int e = blockIdx.x * blockDim.x + threadIdx.x;
    if (e >= N_EDGES) return;
    atomicAdd(&g_cnt_s[senders[e]], 1);
    int pos = atomicAdd(&g_cnt_r[receivers[e]], 1);
    g_epos[e] = pos;
}

__global__ void invsqrt_kernel() {
    int i = blockIdx.x * blockDim.x + threadIdx.x;
    if (i >= N_NODES) return;
    g_invs[i] = rsqrtf(fmaxf((float)g_cnt_s[i], 1.0f));
    g_invr[i] = rsqrtf(fmaxf((float)g_cnt_r[i], 1.0f));
}

// ---------------- CSR build: scan + atomic-free fill ----------------
__global__ void scan_kernel() {   // single block, 1024 threads
    __shared__ int part[1024];
    const int t = threadIdx.x;
    const int CH = (N_NODES + 1023) / 1024;
    const int base = t * CH;
    int s = 0;
    for (int i = 0; i < CH; i++) {
        int idx = base + i;
        if (idx < N_NODES) s += g_cnt_r[idx];
    }
    part[t] = s;
    __syncthreads();
    for (int off = 1; off < 1024; off <<= 1) {
        int v = (t >= off) ? part[t - off] : 0;
        __syncthreads();
        part[t] += v;
        __syncthreads();
    }
    int run = (t == 0) ? 0 : part[t - 1];
    for (int i = 0; i < CH; i++) {
        int idx = base + i;
        if (idx < N_NODES) {
            g_rowstart[idx] = run;
            run += g_cnt_r[idx];
        }
    }
    if (t == 1023) g_rowstart[N_NODES] = run;
}

__global__ void fill_kernel(const int* __restrict__ senders,
                            const int* __restrict__ receivers) {
    int e = blockIdx.x * blockDim.x + threadIdx.x;
    if (e >= N_EDGES) return;
    int r = receivers[e];
    g_elist[g_rowstart[r] + g_epos[e]] = senders[e];
}

// ---------------- embed (vectorized): h = nodes @ W_embed + b ----------------
__global__ void embed_kernel(const float* __restrict__ nodes,
                             const float* __restrict__ We,
                             const float* __restrict__ be) {
    int idx = blockIdx.x * blockDim.x + threadIdx.x;   // N_NODES * 32
    if (idx >= N_NODES * 32) return;
    int n  = idx >> 5;
    int c4 = (idx & 31) * 4;
    float4 acc = *(const float4*)&be[c4];
#pragma unroll
    for (int k = 0; k < IN_FEAT; k++) {
        float nk = nodes[n * IN_FEAT + k];
        float4 w = *(const float4*)&We[k * LATENT + c4];
        acc.x = fmaf(nk, w.x, acc.x);
        acc.y = fmaf(nk, w.y, acc.y);
        acc.z = fmaf(nk, w.z, acc.z);
        acc.w = fmaf(nk, w.w, acc.w);
    }
    *(float4*)&g_h[(size_t)n * LATENT + c4] = acc;
}

// ---------------- W prep: transpose + bf16 hi/lo split ----------------
__global__ void wprep_kernel(const float* __restrict__ mlp_W) {
    int idx = blockIdx.x * blockDim.x + threadIdx.x;  // 6 * 16384
    if (idx >= STEPS * 2 * LATENT * LATENT) return;
    int w = idx >> 14;
    int e = idx & 16383;
    int k = e >> 7;
    int n = e & 127;
    float val = mlp_W[(size_t)w * 16384 + k * 128 + n];
    __nv_bfloat16 h = __float2bfloat16(val);
    __nv_bfloat16 l = __float2bfloat16(val - __bfloat162float(h));
    uint16_t* hi = (uint16_t*)&g_wimg[(size_t)w * 16384];
    uint16_t* lo = hi + 16384;
    hi[n * 128 + k] = *(uint16_t*)&h;
    lo[n * 128 + k] = *(uint16_t*)&l;
}

// ---------------- HMMA bf16x3 GEMM ----------------
#define STR 136
#define SM_A_HI 0
#define SM_A_LO (128 * STR * 2)
#define SM_W_HI (2 * 128 * STR * 2)
#define SM_W_LO (3 * 128 * STR * 2)
#define SM_TOTAL (4 * 128 * STR * 2)     // 139264 bytes

// out_half == 0: C is float[N][128];  out_half == 1: C is __half[N][128]
__global__ void __launch_bounds__(256)
gemm_mma_kernel(const float* __restrict__ A,
                const uint32_t* __restrict__ Wimg,
                const float* __restrict__ bias,
                const float* __restrict__ rowscale,
                void* __restrict__ Cout, int N, int out_half) {
    extern __shared__ __align__(16) char smem[];
    const uint32_t sb = smem_u32(smem);
    const int t = threadIdx.x, lane = t & 31, wid = t >> 5;
    const int warp_m = wid >> 1;
    const int warp_n = wid & 1;
    const int row0 = blockIdx.x * 128;

    // stage W images (repad 64 -> 68 u32/row)
    {
        uint32_t* dh = (uint32_t*)(smem + SM_W_HI);
        uint32_t* dl = (uint32_t*)(smem + SM_W_LO);
        const uint32_t* shi = Wimg;
        const uint32_t* slo = Wimg + 8192;
#pragma unroll
        for (int i = 0; i < 32; i++) {
            int idx = t + i * 256;
            int n  = idx >> 6;
            int kp = idx & 63;
            dh[n * (STR / 2) + kp] = shi[idx];
            dl[n * (STR / 2) + kp] = slo[idx];
        }
    }

    // stage A: fp32 -> bf16 hi/lo
    {
        int row  = t >> 1;
        int k0   = (t & 1) * 64;
        int grow = row0 + row;
        uint32_t* dh = (uint32_t*)(smem + SM_A_HI);
        uint32_t* dl = (uint32_t*)(smem + SM_A_LO);
#pragma unroll
        for (int q = 0; q < 16; q++) {
            float4 v = (grow < N) ? *(const float4*)&A[(size_t)grow * 128 + k0 + q * 4]
                                  : make_float4(0.f, 0.f, 0.f, 0.f);
            float f[4] = {v.x, v.y, v.z, v.w};
#pragma unroll
            for (int p = 0; p < 2; p++) {
                int k = k0 + q * 4 + p * 2;
                __nv_bfloat16 h0 = __float2bfloat16(f[p * 2 + 0]);
                __nv_bfloat16 h1 = __float2bfloat16(f[p * 2 + 1]);
                __nv_bfloat16 l0 = __float2bfloat16(f[p * 2 + 0] - __bfloat162float(h0));
                __nv_bfloat16 l1 = __float2bfloat16(f[p * 2 + 1] - __bfloat162float(h1));
                uint32_t hp = (uint32_t)*(uint16_t*)&h0 | ((uint32_t)*(uint16_t*)&h1 << 16);
                uint32_t lp = (uint32_t)*(uint16_t*)&l0 | ((uint32_t)*(uint16_t*)&l1 << 16);
                dh[row * (STR / 2) + k / 2] = hp;
                dl[row * (STR / 2) + k / 2] = lp;
            }
        }
    }
    __syncthreads();

    float acc[2][8][4];
#pragma unroll
    for (int i = 0; i < 2; i++)
#pragma unroll
        for (int j = 0; j < 8; j++)
#pragma unroll
            for (int q = 0; q < 4; q++) acc[i][j][q] = 0.0f;

    const int a_row_l = (lane & 15);
    const int a_koff  = (lane >> 4) * 8;
    const int b_row_l = ((lane >> 4) & 1) * 8 + (lane & 7);
    const int b_koff  = ((lane >> 3) & 1) * 8;

#pragma unroll
    for (int term = 0; term < 3; term++) {
        const uint32_t aBase = sb + ((term == 2) ? SM_A_LO : SM_A_HI);
        const uint32_t wBase = sb + ((term == 1) ? SM_W_LO : SM_W_HI);
#pragma unroll
        for (int ks = 0; ks < 8; ks++) {
            const int k = ks * 16;
            uint32_t a[2][4];
#pragma unroll
            for (int i = 0; i < 2; i++) {
                int r = warp_m * 32 + i * 16 + a_row_l;
                ldsm4(a[i], aBase + (uint32_t)(r * STR + k + a_koff) * 2);
            }
            uint32_t b[4][4];
#pragma unroll
            for (int jj = 0; jj < 4; jj++) {
                int nr = warp_n * 64 + jj * 16 + b_row_l;
                ldsm4(b[jj], wBase + (uint32_t)(nr * STR + k + b_koff) * 2);
            }
#pragma unroll
            for (int i = 0; i < 2; i++)
#pragma unroll
                for (int j = 0; j < 8; j++)
                    mma16816(acc[i][j], a[i], b[j >> 1][(j & 1) * 2],
                             b[j >> 1][(j & 1) * 2 + 1]);
        }
    }

#pragma unroll
    for (int i = 0; i < 2; i++) {
        int r0 = row0 + warp_m * 32 + i * 16 + (lane >> 2);
        int r1 = r0 + 8;
        float rs0 = 1.0f, rs1 = 1.0f;
        if (rowscale) {
            if (r0 < N) rs0 = rowscale[r0];
            if (r1 < N) rs1 = rowscale[r1];
        }
#pragma unroll
        for (int j = 0; j < 8; j++) {
            int col = warp_n * 64 + j * 8 + (lane & 3) * 2;
            float2 bv = *(const float2*)&bias[col];
            float ox0 = fmaxf(acc[i][j][0] + bv.x, 0.f) * rs0;
            float oy0 = fmaxf(acc[i][j][1] + bv.y, 0.f) * rs0;
            float ox1 = fmaxf(acc[i][j][2] + bv.x, 0.f) * rs1;
            float oy1 = fmaxf(acc[i][j][3] + bv.y, 0.f) * rs1;
            if (out_half) {
                __half* Ch = (__half*)Cout;
                if (r0 < N) {
                    __half2 hh = __floats2half2_rn(ox0, oy0);
                    *(__half2*)&Ch[(size_t)r0 * 128 + col] = hh;
                }
                if (r1 < N) {
                    __half2 hh = __floats2half2_rn(ox1, oy1);
                    *(__half2*)&Ch[(size_t)r1 * 128 + col] = hh;
                }
            } else {
                float* Cf = (float*)Cout;
                if (r0 < N) { float2 o = {ox0, oy0}; *(float2*)&Cf[(size_t)r0 * 128 + col] = o; }
                if (r1 < N) { float2 o = {ox1, oy1}; *(float2*)&Cf[(size_t)r1 * 128 + col] = o; }
            }
        }
    }
}

// ---------------- fused CSR gather (fp16) + skip + LayerNorm (warp per node) ----------------
__global__ void agg_ln_kernel(const float* __restrict__ scale,
                              const float* __restrict__ bias) {
    int gid  = blockIdx.x * blockDim.x + threadIdx.x;
    int n    = gid >> 5;
    int lane = gid & 31;
    if (n >= N_NODES) return;

    const int beg = g_rowstart[n];
    const int end = g_rowstart[n + 1];

    const uint2* x2v = (const uint2*)g_x2h;   // 4 halves per uint2, 32 per row

    float a0 = 0.f, a1 = 0.f, a2 = 0.f, a3 = 0.f;
    int i = beg;
    for (; i + 1 < end; i += 2) {
        int s0 = g_elist[i];
        int s1 = g_elist[i + 1];
        uint2 u0 = x2v[(size_t)s0 * 32 + lane];
        uint2 u1 = x2v[(size_t)s1 * 32 + lane];
        float2 p00 = __half22float2(*(__half2*)&u0.x);
        float2 p01 = __half22float2(*(__half2*)&u0.y);
        float2 p10 = __half22float2(*(__half2*)&u1.x);
        float2 p11 = __half22float2(*(__half2*)&u1.y);
        a0 += p00.x + p10.x;
        a1 += p00.y + p10.y;
        a2 += p01.x + p11.x;
        a3 += p01.y + p11.y;
    }
    if (i < end) {
        int s0 = g_elist[i];
        uint2 u0 = x2v[(size_t)s0 * 32 + lane];
        float2 p00 = __half22float2(*(__half2*)&u0.x);
        float2 p01 = __half22float2(*(__half2*)&u0.y);
        a0 += p00.x; a1 += p00.y; a2 += p01.x; a3 += p01.y;
    }

    float ir = g_invr[n];
    float4 hv = *(const float4*)&g_h[(size_t)n * LATENT + lane * 4];
    float v0 = hv.x + a0 * ir;
    float v1 = hv.y + a1 * ir;
    float v2 = hv.z + a2 * ir;
    float v3 = hv.w + a3 * ir;

    float sum = v0 + v1 + v2 + v3;
    float sq  = v0 * v0 + v1 * v1 + v2 * v2 + v3 * v3;
#pragma unroll
    for (int o = 16; o > 0; o >>= 1) {
        sum += __shfl_xor_sync(0xFFFFFFFF, sum, o);
        sq  += __shfl_xor_sync(0xFFFFFFFF, sq,  o);
    }
    float mean = sum * (1.0f / LATENT);
    float var  = sq * (1.0f / LATENT) - mean * mean;
    float rstd = rsqrtf(var + 1e-6f);
    float4 sc = *(const float4*)&scale[lane * 4];
    float4 bi = *(const float4*)&bias[lane * 4];
    float4 o4;
    o4.x = (v0 - mean) * rstd * sc.x + bi.x;
    o4.y = (v1 - mean) * rstd * sc.y + bi.y;
    o4.z = (v2 - mean) * rstd * sc.z + bi.z;
    o4.w = (v3 - mean) * rstd * sc.w + bi.w;
    *(float4*)&g_h[(size_t)n * LATENT + lane * 4] = o4;
}

// ---------------- decode: out = h @ W_dec + b_dec (warp per node) ----------------
__global__ void decode_kernel(const float* __restrict__ Wd,
                              const float* __restrict__ bd,
                              float* __restrict__ out) {
    int gid  = blockIdx.x * blockDim.x + threadIdx.x;
    int n    = gid >> 5;
    int lane = gid & 31;
    if (n >= N_NODES) return;
    float4 hv = *(const float4*)&g_h[(size_t)n * LATENT + lane * 4];
    float h[4] = {hv.x, hv.y, hv.z, hv.w};
    float acc[IN_FEAT];
#pragma unroll
    for (int o = 0; o < IN_FEAT; o++) acc[o] = 0.0f;
#pragma unroll
    for (int q = 0; q < 4; q++) {
        int k = lane * 4 + q;
#pragma unroll
        for (int o = 0; o < IN_FEAT; o++)
            acc[o] = fmaf(h[q], Wd[k * IN_FEAT + o], acc[o]);
    }
#pragma unroll
    for (int o = 0; o < IN_FEAT; o++) {
#pragma unroll
        for (int off = 16; off > 0; off >>= 1)
            acc[o] += __shfl_xor_sync(0xFFFFFFFF, acc[o], off);
    }
    if (lane < IN_FEAT)
        out[n * IN_FEAT + lane] = acc[lane] + bd[lane];
}

// ---------------- host launch ----------------
extern "C" void kernel_launch(void* const* d_in, const int* in_sizes, int n_in,
                              void* d_out, int out_size) {
    const float* nodes     = (const float*)d_in[0];
    const int*   senders   = (const int*)  d_in[1];
    const int*   receivers = (const int*)  d_in[2];
    const float* W_embed   = (const float*)d_in[3];
    const float* b_embed   = (const float*)d_in[4];
    const float* mlp_W     = (const float*)d_in[5];
    const float* mlp_b     = (const float*)d_in[6];
    const float* ln_scale  = (const float*)d_in[7];
    const float* ln_bias   = (const float*)d_in[8];
    const float* W_dec     = (const float*)d_in[9];
    const float* b_dec     = (const float*)d_in[10];
    float* out = (float*)d_out;

    void *p_h, *p_x1, *p_x2h, *p_invs, *p_cs, *p_cr, *p_wimg;
    cudaGetSymbolAddress(&p_h,    g_h);
    cudaGetSymbolAddress(&p_x1,   g_x1);
    cudaGetSymbolAddress(&p_x2h,  g_x2h);
    cudaGetSymbolAddress(&p_invs, g_invs);
    cudaGetSymbolAddress(&p_cs,   g_cnt_s);
    cudaGetSymbolAddress(&p_cr,   g_cnt_r);
    cudaGetSymbolAddress(&p_wimg, g_wimg);

    cudaFuncSetAttribute(gemm_mma_kernel,
                         cudaFuncAttributeMaxDynamicSharedMemorySize, SM_TOTAL);

    // lazily-created side stream + fork/join events (host resources, no device mem)
    static cudaStream_t s2 = nullptr;
    static cudaEvent_t evFork = nullptr, evJoin = nullptr;
    if (s2 == nullptr) {
        cudaStreamCreate(&s2);
        cudaEventCreateWithFlags(&evFork, cudaEventDisableTiming);
        cudaEventCreateWithFlags(&evJoin, cudaEventDisableTiming);
    }

    // fork: weight images + embed run concurrently with CSR build
    cudaEventRecord(evFork, 0);
    cudaStreamWaitEvent(s2, evFork, 0);
    wprep_kernel<<<(STEPS * 2 * LATENT * LATENT + 255) / 256, 256, 0, s2>>>(mlp_W);
    embed_kernel<<<(N_NODES * 32 + 255) / 256, 256, 0, s2>>>(nodes, W_embed, b_embed);
    cudaEventRecord(evJoin, s2);

    // CSR + normalization prologue (main stream)
    cudaMemsetAsync(p_cs, 0, N_NODES * sizeof(int), 0);
    cudaMemsetAsync(p_cr, 0, N_NODES * sizeof(int), 0);
    degree_kernel<<<(N_EDGES + 255) / 256, 256>>>(senders, receivers);
    invsqrt_kernel<<<(N_NODES + 255) / 256, 256>>>();
    scan_kernel<<<1, 1024>>>();
    fill_kernel<<<(N_EDGES + 255) / 256, 256>>>(senders, receivers);

    // join before the step loop
    cudaStreamWaitEvent(0, evJoin, 0);

    const int gemm_grid = (N_NODES + 127) / 128;
    const int ln_grid = (N_NODES * 32 + 255) / 256;

    for (int step = 0; step < STEPS; step++) {
        const float* b0 = mlp_b + ((size_t)step * 2 + 0) * LATENT;
        const float* b1 = mlp_b + ((size_t)step * 2 + 1) * LATENT;
        const uint32_t* img0 = (const uint32_t*)p_wimg + (size_t)(step * 2 + 0) * 16384;
        const uint32_t* img1 = (const uint32_t*)p_wimg + (size_t)(step * 2 + 1) * 16384;

        gemm_mma_kernel<<<gemm_grid, 256, SM_TOTAL>>>((const float*)p_h, img0, b0,
                                                      nullptr, p_x1, N_NODES, 0);
        gemm_mma_kernel<<<gemm_grid, 256, SM_TOTAL>>>((const float*)p_x1, img1, b1,
                                                      (const float*)p_invs,
                                                      p_x2h, N_NODES, 1);
        agg_ln_kernel<<<ln_grid, 256>>>(ln_scale + step * LATENT, ln_bias + step * LATENT);
    }

    decode_kernel<<<ln_grid, 256>>>(W_dec, b_dec, out);
}